// round 15
// baseline (speedup 1.0000x reference)
#include <cuda_runtime.h>
#include <cuda_bf16.h>

#define SB 2048
#define BB 32
#define DD 512
#define HH 512
#define G4 2048
#define MTOT (SB*BB)

// ---- device scratch (static __device__ globals; no allocations) ----
__device__ float    g_gx[(size_t)MTOT * G4];   // layer-0 input projections
__device__ unsigned g_h0[4][BB * HH];          // layer-0 h, 4-deep ring, packed hi16|lo16
__device__ unsigned g_h1[2][BB * HH];          // layer-1 h, double-buffered, packed
__device__ unsigned g_leaf[8 * 128];           // flag leaves: [0-3]=cntL0 [4-7]=cntL1done

static __device__ __forceinline__ void split_bf16(float v, unsigned short& hi, unsigned short& lo) {
    __nv_bfloat16 h = __float2bfloat16_rn(v);
    float r = v - __bfloat162float(h);
    hi = __bfloat16_as_ushort(h);
    lo = __bfloat16_as_ushort(__float2bfloat16_rn(r));
}

static __device__ __forceinline__ void mma16816(float* d, const unsigned* a, const unsigned* b) {
    asm volatile(
        "mma.sync.aligned.m16n8k16.row.col.f32.bf16.bf16.f32 "
        "{%0,%1,%2,%3}, {%4,%5,%6,%7}, {%8,%9}, {%0,%1,%2,%3};\n"
        : "+f"(d[0]), "+f"(d[1]), "+f"(d[2]), "+f"(d[3])
        : "r"(a[0]), "r"(a[1]), "r"(a[2]), "r"(a[3]), "r"(b[0]), "r"(b[1]));
}

static __device__ __forceinline__ float sigf(float x) { return 1.0f / (1.0f + expf(-x)); }

// poll one 4-leaf bank until every leaf >= tgt; acquire-fence on exit. lane0 use.
static __device__ __forceinline__ void poll4(const unsigned* bank, unsigned tgt) {
    if (tgt == 0u) return;
    bool done = false;
    while (!done) {
        unsigned v0, v1, v2, v3;
        asm volatile("ld.relaxed.gpu.global.u32 %0, [%1];" : "=r"(v0) : "l"(bank + 0 * 128) : "memory");
        asm volatile("ld.relaxed.gpu.global.u32 %0, [%1];" : "=r"(v1) : "l"(bank + 1 * 128) : "memory");
        asm volatile("ld.relaxed.gpu.global.u32 %0, [%1];" : "=r"(v2) : "l"(bank + 2 * 128) : "memory");
        asm volatile("ld.relaxed.gpu.global.u32 %0, [%1];" : "=r"(v3) : "l"(bank + 3 * 128) : "memory");
        done = (v0 >= tgt) & (v1 >= tgt) & (v2 >= tgt) & (v3 >= tgt);
    }
    asm volatile("fence.acq_rel.gpu;" ::: "memory");
}

// ============================================================================
// Layer-0 input projection GEMM: gx[m][n] = X_row(m).Wih0[n] + bias, m = s*32+b
// ============================================================================
__global__ void __launch_bounds__(256) gx_gemm(const float* __restrict__ Xf,
                                               const float* __restrict__ W,
                                               const float* __restrict__ bia,
                                               const float* __restrict__ bib) {
    __shared__ __align__(16) unsigned short sAhi[128][36], sAlo[128][36];
    __shared__ __align__(16) unsigned short sBhi[64][36],  sBlo[64][36];
    __shared__ float sBias[64];

    const int tid = threadIdx.x;
    const int n0 = blockIdx.x * 64, m0 = blockIdx.y * 128;
    if (tid < 64) sBias[tid] = bia[n0 + tid] + bib[n0 + tid];

    const int w = tid >> 5, lane = tid & 31;
    const int wm = w >> 1, wn = w & 1;

    float C[2][4][4];
#pragma unroll
    for (int i = 0; i < 2; i++)
#pragma unroll
        for (int j = 0; j < 4; j++)
#pragma unroll
            for (int k = 0; k < 4; k++) C[i][j][k] = 0.f;

    const int rg = tid >> 3, kq = (tid & 7) * 4;

    for (int kc = 0; kc < 16; kc++) {
        const int k0 = kc * 32;
#pragma unroll
        for (int rr = 0; rr < 4; rr++) {
            const int r = rg + rr * 32, m = m0 + r;
            const int b = m & 31, s = m >> 5;
            const float4 f = *reinterpret_cast<const float4*>(Xf + ((size_t)(b * SB + s)) * DD + k0 + kq);
            const float v[4] = {f.x, f.y, f.z, f.w};
#pragma unroll
            for (int j = 0; j < 4; j++) {
                unsigned short hi, lo; split_bf16(v[j], hi, lo);
                sAhi[r][kq + j] = hi; sAlo[r][kq + j] = lo;
            }
        }
#pragma unroll
        for (int rr = 0; rr < 2; rr++) {
            const int r = rg + rr * 32;
            const float4 f = *reinterpret_cast<const float4*>(W + (size_t)(n0 + r) * DD + k0 + kq);
            const float v[4] = {f.x, f.y, f.z, f.w};
#pragma unroll
            for (int j = 0; j < 4; j++) {
                unsigned short hi, lo; split_bf16(v[j], hi, lo);
                sBhi[r][kq + j] = hi; sBlo[r][kq + j] = lo;
            }
        }
        __syncthreads();

#pragma unroll
        for (int ks = 0; ks < 2; ks++) {
            const int kk = ks * 16 + (lane & 3) * 2;
            unsigned Ah[2][4], Al[2][4], Bh[4][2], Bl[4][2];
#pragma unroll
            for (int mt = 0; mt < 2; mt++) {
                const int r = wm * 32 + mt * 16 + (lane >> 2);
                Ah[mt][0] = *(const unsigned*)&sAhi[r][kk];
                Ah[mt][1] = *(const unsigned*)&sAhi[r + 8][kk];
                Ah[mt][2] = *(const unsigned*)&sAhi[r][kk + 8];
                Ah[mt][3] = *(const unsigned*)&sAhi[r + 8][kk + 8];
                Al[mt][0] = *(const unsigned*)&sAlo[r][kk];
                Al[mt][1] = *(const unsigned*)&sAlo[r + 8][kk];
                Al[mt][2] = *(const unsigned*)&sAlo[r][kk + 8];
                Al[mt][3] = *(const unsigned*)&sAlo[r + 8][kk + 8];
            }
#pragma unroll
            for (int nt = 0; nt < 4; nt++) {
                const int n = wn * 32 + nt * 8 + (lane >> 2);
                Bh[nt][0] = *(const unsigned*)&sBhi[n][kk];
                Bh[nt][1] = *(const unsigned*)&sBhi[n][kk + 8];
                Bl[nt][0] = *(const unsigned*)&sBlo[n][kk];
                Bl[nt][1] = *(const unsigned*)&sBlo[n][kk + 8];
            }
#pragma unroll
            for (int mt = 0; mt < 2; mt++)
#pragma unroll
                for (int nt = 0; nt < 4; nt++) {
                    mma16816(C[mt][nt], Ah[mt], Bh[nt]);
                    mma16816(C[mt][nt], Ah[mt], Bl[nt]);
                    mma16816(C[mt][nt], Al[mt], Bh[nt]);
                }
        }
        __syncthreads();
    }

#pragma unroll
    for (int mt = 0; mt < 2; mt++)
#pragma unroll
        for (int nt = 0; nt < 4; nt++) {
            const int r  = m0 + wm * 32 + mt * 16 + (lane >> 2);
            const int cn = wn * 32 + nt * 8 + (lane & 3) * 2;
            const float b0v = sBias[cn], b1v = sBias[cn + 1];
            *reinterpret_cast<float2*>(g_gx + (size_t)r * G4 + n0 + cn) =
                make_float2(C[mt][nt][0] + b0v, C[mt][nt][1] + b1v);
            *reinterpret_cast<float2*>(g_gx + (size_t)(r + 8) * G4 + n0 + cn) =
                make_float2(C[mt][nt][2] + b0v, C[mt][nt][3] + b1v);
        }
}

__global__ void zero_bar() {
    if (threadIdx.x < 8) g_leaf[threadIdx.x * 128] = 0;
}

// ============================================================================
// Fused 2-layer pipelined recurrence with WARP-AUTONOMOUS staging:
// each warp polls only its own deps, cp.async-stages ONLY its K-slice into its
// private sH region, and MMAs on it. Two CTA syncs/round (publish, store).
// Blocks 0-63 = layer 0 (t=r); blocks 64-127 = layer 1 (t=r-1, fused K=1024).
// ============================================================================
template <int LAY>
static __device__ __forceinline__ void run_layer(
    const float* __restrict__ Wa,   // LAY0: Whh0 ; LAY1: Wih1
    const float* __restrict__ Wb,   // LAY1: Whh1
    const float* __restrict__ bi, const float* __restrict__ bh,
    float* __restrict__ dout, unsigned* sH, float* sP)
{
    const int tid = threadIdx.x;
    const int ug = blockIdx.x & 63, u0 = ug * 8;
    const int ws = tid >> 5, lane = tid & 31;
    const int lf = (int)(blockIdx.x & 3);
    constexpr int KSL = LAY ? 128 : 64;   // K words per warp slice
    constexpr int NKS = KSL / 16;         // 8 (L1) or 4 (L0)
    constexpr int RSW = KSL + 4;          // slice row stride (banks spread)

    // ---- preload register-resident split-bf16 weight fragments (all 4 gates) ----
    unsigned Bhi[NKS][4][2], Blo[NKS][4][2];
#pragma unroll
    for (int gg = 0; gg < 4; gg++) {
        const int row = gg * 512 + u0 + (lane >> 2);
        const float* wr;
        if (LAY == 0) wr = Wa + (size_t)row * HH + ws * KSL;
        else          wr = (ws < 4) ? (Wa + (size_t)row * HH + ws * 128)
                                    : (Wb + (size_t)row * HH + (ws - 4) * 128);
#pragma unroll
        for (int ks = 0; ks < NKS; ks++) {
            const int k = ks * 16 + (lane & 3) * 2;
            unsigned short h0, l0, h1, l1;
            split_bf16(wr[k], h0, l0);     split_bf16(wr[k + 1], h1, l1);
            Bhi[ks][gg][0] = (unsigned)h0 | ((unsigned)h1 << 16);
            Blo[ks][gg][0] = (unsigned)l0 | ((unsigned)l1 << 16);
            split_bf16(wr[k + 8], h0, l0); split_bf16(wr[k + 9], h1, l1);
            Bhi[ks][gg][1] = (unsigned)h0 | ((unsigned)h1 << 16);
            Blo[ks][gg][1] = (unsigned)l0 | ((unsigned)l1 << 16);
        }
    }

    float cst = 0.f;
    const int bl = tid >> 3, ul = tid & 7;   // (batch, unit) for elementwise

    float pg[4];
    if (LAY == 0) {   // prefetch gx for t=0
        const float* gp = g_gx + (size_t)bl * G4 + u0 + ul;
        pg[0] = __ldcs(gp);        pg[1] = __ldcs(gp + 512);
        pg[2] = __ldcs(gp + 1024); pg[3] = __ldcs(gp + 1536);
    } else {          // constant bias
        pg[0] = bi[u0 + ul]        + bh[u0 + ul];
        pg[1] = bi[512 + u0 + ul]  + bh[512 + u0 + ul];
        pg[2] = bi[1024 + u0 + ul] + bh[1024 + u0 + ul];
        pg[3] = bi[1536 + u0 + ul] + bh[1536 + u0 + ul];
    }

    const int rbeg = LAY ? 1 : 0;
    const int rend = LAY ? SB : SB - 1;   // inclusive

    const int r0 = lane >> 2, kq = (lane & 3) * 2;
    const int koff = (LAY == 0) ? (ws * KSL) : ((ws & 3) * 128);  // gmem K offset
    unsigned* sHw = sH + (size_t)ws * 32 * RSW;                   // this warp's slice
    const unsigned sHw_u32 = (unsigned)__cvta_generic_to_shared(sHw);

    for (int r = rbeg; r <= rend; r++) {
        const int t = LAY ? (r - 1) : r;

        // ---- per-warp dependency polls (lane 0) ----
        if (LAY == 0) {
            if (lane == 0) {
                poll4(g_leaf, 16u * (unsigned)r);                          // h0 RAW
                if (r >= 2) poll4(g_leaf + 4 * 128, 16u * (unsigned)(r - 2)); // ring WAR
            }
        } else {
            if (ws < 4) { if (lane == 0) poll4(g_leaf, 16u * (unsigned)r); }            // h0 ready
            else        { if (lane == 0) poll4(g_leaf + 4 * 128, 16u * (unsigned)(r - 1)); } // h1 ready
        }
        __syncwarp();

        // ---- per-warp A source ----
        const unsigned* asrc = nullptr;
        if (LAY == 0) { if (t > 0) asrc = g_h0[(t - 1) & 3]; }
        else {
            if (ws < 4) asrc = g_h0[t & 3];
            else if (t > 0) asrc = g_h1[(t - 1) & 1];
        }

        if (asrc) {
            // ---- stage own slice via cp.async (warp-local) ----
            const unsigned* src = asrc + koff;
            constexpr int C4 = KSL / 4;                 // uint4 per row
#pragma unroll
            for (int i = 0; i < C4; i++) {              // 32 lanes x C4 iters
                const int flat = lane + i * 32;
                const int row = flat / C4, c4 = flat % C4;
                const unsigned dst = sHw_u32 + (unsigned)(row * RSW + c4 * 4) * 4u;
                const unsigned* gsrc = src + (size_t)row * HH + c4 * 4;
                asm volatile("cp.async.cg.shared.global [%0], [%1], 16;\n"
                             :: "r"(dst), "l"(gsrc));
            }
            asm volatile("cp.async.commit_group;\n" ::: "memory");
            asm volatile("cp.async.wait_group 0;\n" ::: "memory");
            __syncwarp();

            // ---- MMA on own slice (slice-local coords) ----
            float C[2][4][4];
#pragma unroll
            for (int i = 0; i < 2; i++)
#pragma unroll
                for (int j = 0; j < 4; j++)
#pragma unroll
                    for (int k = 0; k < 4; k++) C[i][j][k] = 0.f;

#pragma unroll
            for (int ks = 0; ks < NKS; ks++) {
                const int kk = ks * 16 + kq;
                unsigned ah[2][4], al[2][4];
#pragma unroll
                for (int mt = 0; mt < 2; mt++) {
                    const int m = mt * 16 + r0;
                    uint2 p0 = *(const uint2*)&sHw[m * RSW + kk];
                    uint2 p1 = *(const uint2*)&sHw[(m + 8) * RSW + kk];
                    uint2 p2 = *(const uint2*)&sHw[m * RSW + kk + 8];
                    uint2 p3 = *(const uint2*)&sHw[(m + 8) * RSW + kk + 8];
                    ah[mt][0] = __byte_perm(p0.x, p0.y, 0x7632); al[mt][0] = __byte_perm(p0.x, p0.y, 0x5410);
                    ah[mt][1] = __byte_perm(p1.x, p1.y, 0x7632); al[mt][1] = __byte_perm(p1.x, p1.y, 0x5410);
                    ah[mt][2] = __byte_perm(p2.x, p2.y, 0x7632); al[mt][2] = __byte_perm(p2.x, p2.y, 0x5410);
                    ah[mt][3] = __byte_perm(p3.x, p3.y, 0x7632); al[mt][3] = __byte_perm(p3.x, p3.y, 0x5410);
                }
#pragma unroll
                for (int mt = 0; mt < 2; mt++)
#pragma unroll
                    for (int gg = 0; gg < 4; gg++) {
                        mma16816(C[mt][gg], ah[mt], Bhi[ks][gg]);
                        mma16816(C[mt][gg], ah[mt], Blo[ks][gg]);
                        mma16816(C[mt][gg], al[mt], Bhi[ks][gg]);
                    }
            }
            // publish partials: sP[ws][gate][batch 32][unit 8]
            const int cc = (lane & 3) * 2;
#pragma unroll
            for (int mt = 0; mt < 2; mt++)
#pragma unroll
                for (int gg = 0; gg < 4; gg++) {
                    float* base = sP + (size_t)((ws * 4 + gg) * 32) * 8;
                    const int m = mt * 16 + r0;
                    base[m * 8 + cc]           = C[mt][gg][0];
                    base[m * 8 + cc + 1]       = C[mt][gg][1];
                    base[(m + 8) * 8 + cc]     = C[mt][gg][2];
                    base[(m + 8) * 8 + cc + 1] = C[mt][gg][3];
                }
        } else {
            float* basew = sP + (size_t)(ws * 4) * 256;
            for (int i = lane; i < 1024; i += 32) basew[i] = 0.f;
        }
        __syncthreads();   // A: all partials visible

        // ---- LSTM elementwise: sum 8 K-slice partials per gate ----
        {
            float gv4[4];
#pragma unroll
            for (int gg = 0; gg < 4; gg++) {
                float s = pg[gg];
#pragma unroll
                for (int wsl = 0; wsl < 8; wsl++)
                    s += sP[(size_t)((wsl * 4 + gg) * 32 + bl) * 8 + ul];
                gv4[gg] = s;
            }
            cst = sigf(gv4[1]) * cst + sigf(gv4[0]) * tanhf(gv4[2]);
            const float h = sigf(gv4[3]) * tanhf(cst);
            unsigned short hh, hl; split_bf16(h, hh, hl);
            const unsigned hp = ((unsigned)hh << 16) | (unsigned)hl;
            if (LAY == 0) {
                __stcg(&g_h0[t & 3][bl * HH + u0 + ul], hp);
                if (t + 1 < SB) {
                    const float* gp = g_gx + ((size_t)(t + 1) * BB + bl) * G4 + u0 + ul;
                    pg[0] = __ldcs(gp);        pg[1] = __ldcs(gp + 512);
                    pg[2] = __ldcs(gp + 1024); pg[3] = __ldcs(gp + 1536);
                }
            } else {
                __stcg(&g_h1[t & 1][bl * HH + u0 + ul], hp);
                __stcs(&dout[((size_t)bl * SB + t) * HH + u0 + ul], h);
            }
        }
        __syncthreads();   // B: h stores done before release

        if (tid == 0)
            asm volatile("red.release.gpu.global.add.u32 [%0], 1;"
                         :: "l"(&g_leaf[((LAY ? 4 : 0) + lf) * 128]) : "memory");
    }
}

__global__ void __launch_bounds__(256, 1) lstm_fused(
    const float* __restrict__ Whh0, const float* __restrict__ Wih1,
    const float* __restrict__ Whh1,
    const float* __restrict__ bi1,  const float* __restrict__ bh1,
    float* __restrict__ dout)
{
    extern __shared__ unsigned smem[];
    // sH sized for the larger (L1) layout: 8 warps * 32 rows * (128+4) words
    unsigned* sH = smem;
    float* sP = (float*)(smem + 8 * 32 * 132);
    if (blockIdx.x < 64) run_layer<0>(Whh0, Whh0, Whh0, Whh0, dout, sH, sP);
    else                 run_layer<1>(Wih1, Whh1, bi1, bh1, dout, sH, sP);
}

extern "C" void kernel_launch(void* const* d_in, const int* in_sizes, int n_in,
                              void* d_out, int out_size) {
    const float* X   = (const float*)d_in[0];
    const float* Wih = (const float*)d_in[1];
    const float* Whh = (const float*)d_in[2];
    const float* bih = (const float*)d_in[3];
    const float* bhh = (const float*)d_in[4];
    float* out = (float*)d_out;

    const int smem_bytes = (8 * 32 * 132 + 8 * 4 * 32 * 8) * 4;  // 135168 + 32768 = 167,936 B
    cudaFuncSetAttribute(lstm_fused, cudaFuncAttributeMaxDynamicSharedMemorySize, smem_bytes);

    dim3 gg(32, 512);
    gx_gemm<<<gg, 256>>>(X, Wih, bih, bhh);        // layer-0 input projections
    zero_bar<<<1, 32>>>();
    lstm_fused<<<128, 256, smem_bytes>>>(Whh,                      // Whh0
                                         Wih + (size_t)G4 * DD,    // Wih1
                                         Whh + (size_t)G4 * HH,    // Whh1
                                         bih + G4, bhh + G4, out);
}

// round 17
// speedup vs baseline: 1.0704x; 1.0704x over previous
#include <cuda_runtime.h>
#include <cuda_bf16.h>

#define SB 2048
#define BB 32
#define DD 512
#define HH 512
#define G4 2048
#define MTOT (SB*BB)

// ---- device scratch (static __device__ globals; no allocations) ----
__device__ float    g_gx[(size_t)MTOT * G4];   // layer-0 input projections
__device__ unsigned g_h0[2][BB * HH];          // layer-0 h, double-buffered, packed hi16|lo16
__device__ unsigned g_h1[2][BB * HH];          // layer-1 h, double-buffered, packed
__device__ unsigned g_leaf[12 * 128];          // [0-3]=cntL0 [4-7]=cntL1staged [8-11]=cntL1done

static __device__ __forceinline__ void split_bf16(float v, unsigned short& hi, unsigned short& lo) {
    __nv_bfloat16 h = __float2bfloat16_rn(v);
    float r = v - __bfloat162float(h);
    hi = __bfloat16_as_ushort(h);
    lo = __bfloat16_as_ushort(__float2bfloat16_rn(r));
}

static __device__ __forceinline__ void mma16816(float* d, const unsigned* a, const unsigned* b) {
    asm volatile(
        "mma.sync.aligned.m16n8k16.row.col.f32.bf16.bf16.f32 "
        "{%0,%1,%2,%3}, {%4,%5,%6,%7}, {%8,%9}, {%0,%1,%2,%3};\n"
        : "+f"(d[0]), "+f"(d[1]), "+f"(d[2]), "+f"(d[3])
        : "r"(a[0]), "r"(a[1]), "r"(a[2]), "r"(a[3]), "r"(b[0]), "r"(b[1]));
}

static __device__ __forceinline__ float sigf(float x) { return 1.0f / (1.0f + expf(-x)); }

// poll two 4-leaf banks until bank0 >= t0 and bankX >= t1 on every leaf (tid0 only)
static __device__ __forceinline__ void poll_flags(const unsigned* bank0, const unsigned* bankX,
                                                  unsigned t0, unsigned t1) {
    bool done = false;
    while (!done) {
        unsigned a0, a1, a2, a3, b0, b1, b2, b3;
        asm volatile("ld.relaxed.gpu.global.u32 %0, [%1];" : "=r"(a0) : "l"(bank0 + 0 * 128) : "memory");
        asm volatile("ld.relaxed.gpu.global.u32 %0, [%1];" : "=r"(a1) : "l"(bank0 + 1 * 128) : "memory");
        asm volatile("ld.relaxed.gpu.global.u32 %0, [%1];" : "=r"(a2) : "l"(bank0 + 2 * 128) : "memory");
        asm volatile("ld.relaxed.gpu.global.u32 %0, [%1];" : "=r"(a3) : "l"(bank0 + 3 * 128) : "memory");
        asm volatile("ld.relaxed.gpu.global.u32 %0, [%1];" : "=r"(b0) : "l"(bankX + 0 * 128) : "memory");
        asm volatile("ld.relaxed.gpu.global.u32 %0, [%1];" : "=r"(b1) : "l"(bankX + 1 * 128) : "memory");
        asm volatile("ld.relaxed.gpu.global.u32 %0, [%1];" : "=r"(b2) : "l"(bankX + 2 * 128) : "memory");
        asm volatile("ld.relaxed.gpu.global.u32 %0, [%1];" : "=r"(b3) : "l"(bankX + 3 * 128) : "memory");
        done = (a0 >= t0) & (a1 >= t0) & (a2 >= t0) & (a3 >= t0)
             & (b0 >= t1) & (b1 >= t1) & (b2 >= t1) & (b3 >= t1);
    }
    asm volatile("fence.acq_rel.gpu;" ::: "memory");
}

// ============================================================================
// Layer-0 input projection GEMM: gx[m][n] = X_row(m).Wih0[n] + bias, m = s*32+b
// ============================================================================
__global__ void __launch_bounds__(256) gx_gemm(const float* __restrict__ Xf,
                                               const float* __restrict__ W,
                                               const float* __restrict__ bia,
                                               const float* __restrict__ bib) {
    __shared__ __align__(16) unsigned short sAhi[128][36], sAlo[128][36];
    __shared__ __align__(16) unsigned short sBhi[64][36],  sBlo[64][36];
    __shared__ float sBias[64];

    const int tid = threadIdx.x;
    const int n0 = blockIdx.x * 64, m0 = blockIdx.y * 128;
    if (tid < 64) sBias[tid] = bia[n0 + tid] + bib[n0 + tid];

    const int w = tid >> 5, lane = tid & 31;
    const int wm = w >> 1, wn = w & 1;

    float C[2][4][4];
#pragma unroll
    for (int i = 0; i < 2; i++)
#pragma unroll
        for (int j = 0; j < 4; j++)
#pragma unroll
            for (int k = 0; k < 4; k++) C[i][j][k] = 0.f;

    const int rg = tid >> 3, kq = (tid & 7) * 4;

    for (int kc = 0; kc < 16; kc++) {
        const int k0 = kc * 32;
#pragma unroll
        for (int rr = 0; rr < 4; rr++) {
            const int r = rg + rr * 32, m = m0 + r;
            const int b = m & 31, s = m >> 5;
            const float4 f = *reinterpret_cast<const float4*>(Xf + ((size_t)(b * SB + s)) * DD + k0 + kq);
            const float v[4] = {f.x, f.y, f.z, f.w};
#pragma unroll
            for (int j = 0; j < 4; j++) {
                unsigned short hi, lo; split_bf16(v[j], hi, lo);
                sAhi[r][kq + j] = hi; sAlo[r][kq + j] = lo;
            }
        }
#pragma unroll
        for (int rr = 0; rr < 2; rr++) {
            const int r = rg + rr * 32;
            const float4 f = *reinterpret_cast<const float4*>(W + (size_t)(n0 + r) * DD + k0 + kq);
            const float v[4] = {f.x, f.y, f.z, f.w};
#pragma unroll
            for (int j = 0; j < 4; j++) {
                unsigned short hi, lo; split_bf16(v[j], hi, lo);
                sBhi[r][kq + j] = hi; sBlo[r][kq + j] = lo;
            }
        }
        __syncthreads();

#pragma unroll
        for (int ks = 0; ks < 2; ks++) {
            const int kk = ks * 16 + (lane & 3) * 2;
            unsigned Ah[2][4], Al[2][4], Bh[4][2], Bl[4][2];
#pragma unroll
            for (int mt = 0; mt < 2; mt++) {
                const int r = wm * 32 + mt * 16 + (lane >> 2);
                Ah[mt][0] = *(const unsigned*)&sAhi[r][kk];
                Ah[mt][1] = *(const unsigned*)&sAhi[r + 8][kk];
                Ah[mt][2] = *(const unsigned*)&sAhi[r][kk + 8];
                Ah[mt][3] = *(const unsigned*)&sAhi[r + 8][kk + 8];
                Al[mt][0] = *(const unsigned*)&sAlo[r][kk];
                Al[mt][1] = *(const unsigned*)&sAlo[r + 8][kk];
                Al[mt][2] = *(const unsigned*)&sAlo[r][kk + 8];
                Al[mt][3] = *(const unsigned*)&sAlo[r + 8][kk + 8];
            }
#pragma unroll
            for (int nt = 0; nt < 4; nt++) {
                const int n = wn * 32 + nt * 8 + (lane >> 2);
                Bh[nt][0] = *(const unsigned*)&sBhi[n][kk];
                Bh[nt][1] = *(const unsigned*)&sBhi[n][kk + 8];
                Bl[nt][0] = *(const unsigned*)&sBlo[n][kk];
                Bl[nt][1] = *(const unsigned*)&sBlo[n][kk + 8];
            }
#pragma unroll
            for (int mt = 0; mt < 2; mt++)
#pragma unroll
                for (int nt = 0; nt < 4; nt++) {
                    mma16816(C[mt][nt], Ah[mt], Bh[nt]);
                    mma16816(C[mt][nt], Ah[mt], Bl[nt]);
                    mma16816(C[mt][nt], Al[mt], Bh[nt]);
                }
        }
        __syncthreads();
    }

#pragma unroll
    for (int mt = 0; mt < 2; mt++)
#pragma unroll
        for (int nt = 0; nt < 4; nt++) {
            const int r  = m0 + wm * 32 + mt * 16 + (lane >> 2);
            const int cn = wn * 32 + nt * 8 + (lane & 3) * 2;
            const float b0v = sBias[cn], b1v = sBias[cn + 1];
            *reinterpret_cast<float2*>(g_gx + (size_t)r * G4 + n0 + cn) =
                make_float2(C[mt][nt][0] + b0v, C[mt][nt][1] + b1v);
            *reinterpret_cast<float2*>(g_gx + (size_t)(r + 8) * G4 + n0 + cn) =
                make_float2(C[mt][nt][2] + b0v, C[mt][nt][3] + b1v);
        }
}

__global__ void zero_bar() {
    if (threadIdx.x < 12) g_leaf[threadIdx.x * 128] = 0;
}

// ============================================================================
// Fused 2-layer pipelined recurrence — round-9 structure (CTA-wide staging,
// 3-bank decoupled flags) widened to 512 threads / 16 warps: per-warp K-slice
// halves (L1: 64, L0: 32), halving MMA/LDS/PRMT streams and staging work.
// Blocks 0-63 = layer 0 (t=r); blocks 64-127 = layer 1 (t=r-1, fused K=1024).
// ============================================================================
template <int LAY>
static __device__ __forceinline__ void run_layer(
    const float* __restrict__ Wa,   // LAY0: Whh0 ; LAY1: Wih1
    const float* __restrict__ Wb,   // LAY1: Whh1
    const float* __restrict__ bi, const float* __restrict__ bh,
    float* __restrict__ dout, unsigned* sH, float* sP)
{
    const int tid = threadIdx.x;
    const int ug = blockIdx.x & 63, u0 = ug * 8;
    const int ws = tid >> 5, lane = tid & 31;
    const int lf = (int)(blockIdx.x & 3);
    constexpr int KSL = LAY ? 64 : 32;    // k-range per warp (16 warps)
    constexpr int NKS = KSL / 16;         // 4 (L1) or 2 (L0)
    constexpr int RS  = LAY ? 1036 : 524; // sH row stride in words

    // ---- preload register-resident split-bf16 weight fragments (all 4 gates) ----
    unsigned Bhi[NKS][4][2], Blo[NKS][4][2];
#pragma unroll
    for (int gg = 0; gg < 4; gg++) {
        const int row = gg * 512 + u0 + (lane >> 2);
        const float* wr;
        if (LAY == 0) wr = Wa + (size_t)row * HH + ws * KSL;
        else          wr = (ws < 8) ? (Wa + (size_t)row * HH + ws * 64)
                                    : (Wb + (size_t)row * HH + (ws - 8) * 64);
#pragma unroll
        for (int ks = 0; ks < NKS; ks++) {
            const int k = ks * 16 + (lane & 3) * 2;
            unsigned short h0, l0, h1, l1;
            split_bf16(wr[k], h0, l0);     split_bf16(wr[k + 1], h1, l1);
            Bhi[ks][gg][0] = (unsigned)h0 | ((unsigned)h1 << 16);
            Blo[ks][gg][0] = (unsigned)l0 | ((unsigned)l1 << 16);
            split_bf16(wr[k + 8], h0, l0); split_bf16(wr[k + 9], h1, l1);
            Bhi[ks][gg][1] = (unsigned)h0 | ((unsigned)h1 << 16);
            Blo[ks][gg][1] = (unsigned)l0 | ((unsigned)l1 << 16);
        }
    }

    float cst = 0.f;
    const int bl = (tid >> 3) & 31, ul = tid & 7;   // (batch, unit) for tid<256

    float pg[4];
    if (LAY == 0) {   // prefetch gx for t=0
        const float* gp = g_gx + (size_t)bl * G4 + u0 + ul;
        pg[0] = __ldcs(gp);        pg[1] = __ldcs(gp + 512);
        pg[2] = __ldcs(gp + 1024); pg[3] = __ldcs(gp + 1536);
    } else {          // constant bias
        pg[0] = bi[u0 + ul]        + bh[u0 + ul];
        pg[1] = bi[512 + u0 + ul]  + bh[512 + u0 + ul];
        pg[2] = bi[1024 + u0 + ul] + bh[1024 + u0 + ul];
        pg[3] = bi[1536 + u0 + ul] + bh[1536 + u0 + ul];
    }

    // L1 initial wait: L0 must finish round 0 before L1 round 1 reads h0[0]
    if (LAY == 1) {
        if (tid == 0) poll_flags(g_leaf, g_leaf + 8 * 128, 16u, 0u);
        __syncthreads();
    }

    const int rbeg = LAY ? 1 : 0;
    const int rend = LAY ? SB : SB - 1;   // inclusive

    const int r0 = lane >> 2, kq = (lane & 3) * 2;

    for (int r = rbeg; r <= rend; r++) {
        const int t = LAY ? (r - 1) : r;

        // ---- stage packed h into SMEM (CTA-wide, coalesced, high MLP) ----
        if (LAY == 0) {
            const uint4* src = (t > 0) ? (const uint4*)g_h0[(t + 1) & 1] : nullptr;
#pragma unroll
            for (int j = 0; j < 8; j++) {
                const int i4 = tid + j * 512;
                uint4 v = src ? __ldcg(src + i4) : make_uint4(0, 0, 0, 0);
                const int row = i4 >> 7, c4 = i4 & 127;
                *reinterpret_cast<uint4*>(&sH[row * RS + c4 * 4]) = v;
            }
        } else {
            const uint4* srcA = (const uint4*)g_h0[t & 1];
            const uint4* srcB = (t > 0) ? (const uint4*)g_h1[(t + 1) & 1] : nullptr;
#pragma unroll
            for (int j = 0; j < 8; j++) {
                const int i4 = tid + j * 512;
                const int row = i4 >> 7, c4 = i4 & 127;
                uint4 va = __ldcg(srcA + i4);
                *reinterpret_cast<uint4*>(&sH[row * RS + c4 * 4]) = va;
                uint4 vb = srcB ? __ldcg(srcB + i4) : make_uint4(0, 0, 0, 0);
                *reinterpret_cast<uint4*>(&sH[row * RS + 512 + c4 * 4]) = vb;
            }
        }
        __syncthreads();

        // L1: signal "staged" (done reading h0/h1 buffers) -> unblocks L0's WAR
        if (LAY == 1 && tid == 0)
            asm volatile("red.relaxed.gpu.global.add.u32 [%0], 1;"
                         :: "l"(&g_leaf[(4 + lf) * 128]) : "memory");

        // ---- MMA: warp owns K-slice, computes all 4 gates; A split once ----
        {
            float C[2][4][4];
#pragma unroll
            for (int i = 0; i < 2; i++)
#pragma unroll
                for (int j = 0; j < 4; j++)
#pragma unroll
                    for (int k = 0; k < 4; k++) C[i][j][k] = 0.f;

            const int kbase = ws * KSL + kq;
#pragma unroll
            for (int ks = 0; ks < NKS; ks++) {
                const int kk = kbase + ks * 16;
                unsigned ah[2][4], al[2][4];
#pragma unroll
                for (int mt = 0; mt < 2; mt++) {
                    const int m = mt * 16 + r0;
                    uint2 p0 = *(const uint2*)&sH[m * RS + kk];
                    uint2 p1 = *(const uint2*)&sH[(m + 8) * RS + kk];
                    uint2 p2 = *(const uint2*)&sH[m * RS + kk + 8];
                    uint2 p3 = *(const uint2*)&sH[(m + 8) * RS + kk + 8];
                    ah[mt][0] = __byte_perm(p0.x, p0.y, 0x7632); al[mt][0] = __byte_perm(p0.x, p0.y, 0x5410);
                    ah[mt][1] = __byte_perm(p1.x, p1.y, 0x7632); al[mt][1] = __byte_perm(p1.x, p1.y, 0x5410);
                    ah[mt][2] = __byte_perm(p2.x, p2.y, 0x7632); al[mt][2] = __byte_perm(p2.x, p2.y, 0x5410);
                    ah[mt][3] = __byte_perm(p3.x, p3.y, 0x7632); al[mt][3] = __byte_perm(p3.x, p3.y, 0x5410);
                }
#pragma unroll
                for (int mt = 0; mt < 2; mt++)
#pragma unroll
                    for (int gg = 0; gg < 4; gg++) {
                        mma16816(C[mt][gg], ah[mt], Bhi[ks][gg]);
                        mma16816(C[mt][gg], ah[mt], Blo[ks][gg]);
                        mma16816(C[mt][gg], al[mt], Bhi[ks][gg]);
                    }
            }
            // publish partials: sP[ws][gate][batch 32][unit 8]
            const int cc = (lane & 3) * 2;
#pragma unroll
            for (int mt = 0; mt < 2; mt++)
#pragma unroll
                for (int gg = 0; gg < 4; gg++) {
                    float* base = sP + (size_t)((ws * 4 + gg) * 32) * 8;
                    const int m = mt * 16 + r0;
                    base[m * 8 + cc]           = C[mt][gg][0];
                    base[m * 8 + cc + 1]       = C[mt][gg][1];
                    base[(m + 8) * 8 + cc]     = C[mt][gg][2];
                    base[(m + 8) * 8 + cc + 1] = C[mt][gg][3];
                }
        }
        __syncthreads();

        // ---- LSTM elementwise: sum 16 K-slice partials per gate (tid<256) ----
        if (tid < 256) {
            float gv4[4];
#pragma unroll
            for (int gg = 0; gg < 4; gg++) {
                float s = pg[gg];
#pragma unroll
                for (int wsl = 0; wsl < 16; wsl++)
                    s += sP[(size_t)((wsl * 4 + gg) * 32 + bl) * 8 + ul];
                gv4[gg] = s;
            }
            cst = sigf(gv4[1]) * cst + sigf(gv4[0]) * tanhf(gv4[2]);
            const float h = sigf(gv4[3]) * tanhf(cst);
            unsigned short hh, hl; split_bf16(h, hh, hl);
            const unsigned hp = ((unsigned)hh << 16) | (unsigned)hl;
            if (LAY == 0) {
                __stcg(&g_h0[t & 1][bl * HH + u0 + ul], hp);
                if (t + 1 < SB) {   // prefetch next gx during flag wait
                    const float* gp = g_gx + ((size_t)(t + 1) * BB + bl) * G4 + u0 + ul;
                    pg[0] = __ldcs(gp);        pg[1] = __ldcs(gp + 512);
                    pg[2] = __ldcs(gp + 1024); pg[3] = __ldcs(gp + 1536);
                }
            } else {
                __stcg(&g_h1[t & 1][bl * HH + u0 + ul], hp);
                __stcs(&dout[((size_t)bl * SB + t) * HH + u0 + ul], h);
            }
        }
        __syncthreads();

        // ---- arrive (release own h stores) + wait for next round's deps ----
        if (tid == 0) {
            asm volatile("red.release.gpu.global.add.u32 [%0], 1;"
                         :: "l"(&g_leaf[((LAY ? 8 : 0) + lf) * 128]) : "memory");
            if (r < rend) {
                // next round rho = r+1: need cntL0 >= 16*rho and partner >= 16*(rho-1)
                poll_flags(g_leaf, g_leaf + (LAY ? 8 : 4) * 128,
                           16u * (unsigned)(r + 1), 16u * (unsigned)r);
            }
        }
        __syncthreads();
    }
}

__global__ void __launch_bounds__(512, 1) lstm_fused(
    const float* __restrict__ Whh0, const float* __restrict__ Wih1,
    const float* __restrict__ Whh1,
    const float* __restrict__ bi1,  const float* __restrict__ bh1,
    float* __restrict__ dout)
{
    extern __shared__ unsigned smem[];
    unsigned* sH = smem;                       // L1 view: 32 x 1036 words
    float* sP = (float*)(smem + 32 * 1036);    // 16 x 4 x 32 x 8 floats (64 KB)
    if (blockIdx.x < 64) run_layer<0>(Whh0, Whh0, Whh0, Whh0, dout, sH, sP);
    else                 run_layer<1>(Wih1, Whh1, bi1, bh1, dout, sH, sP);
}

extern "C" void kernel_launch(void* const* d_in, const int* in_sizes, int n_in,
                              void* d_out, int out_size) {
    const float* X   = (const float*)d_in[0];
    const float* Wih = (const float*)d_in[1];
    const float* Whh = (const float*)d_in[2];
    const float* bih = (const float*)d_in[3];
    const float* bhh = (const float*)d_in[4];
    float* out = (float*)d_out;

    const int smem_bytes = (32 * 1036 + 16 * 4 * 32 * 8) * 4;  // 132608 + 65536 = 198,144 B
    cudaFuncSetAttribute(lstm_fused, cudaFuncAttributeMaxDynamicSharedMemorySize, smem_bytes);

    dim3 gg(32, 512);
    gx_gemm<<<gg, 256>>>(X, Wih, bih, bhh);        // layer-0 input projections
    zero_bar<<<1, 32>>>();
    lstm_fused<<<128, 512, smem_bytes>>>(Whh,                      // Whh0
                                         Wih + (size_t)G4 * DD,    // Wih1
                                         Whh + (size_t)G4 * HH,    // Whh1
                                         bih + G4, bhh + G4, out);
}